// round 7
// baseline (speedup 1.0000x reference)
#include <cuda_runtime.h>
#include <cuda_bf16.h>
#include <cstdint>

// Inputs (metadata order):
//   d_in[0] = x      float32 [262144]  (1 MB, random-gathered, L2-resident)
//   d_in[1] = A_vals float32 [NNZ]     (streamed -> TMA bulk copy to smem)
//   d_in[2] = A_rows int32   [NNZ]     (streamed -> TMA bulk copy to smem)
//   d_in[3] = A_cols int32   [NNZ]     (streamed -> TMA bulk copy to smem)
// Output: float32 [262144]
//
// R7: move the 100MB index/value stream off the L1tex global port (co-binding
// with gathers+atomics at ~1 wavefront/cyc/SM) onto the TMA engine + smem
// crossbar. Gather + RED scatter unchanged (irreducible for unsorted COO).

#define TILE_NNZ   1024          // per CTA: 256 threads x 4 nnz
#define TILE_BYTES (TILE_NNZ * 4)

__device__ __forceinline__ uint32_t smem_u32(const void* p) {
    uint32_t a;
    asm("{ .reg .u64 t; cvta.to.shared.u64 t, %1; cvt.u32.u64 %0, t; }"
        : "=r"(a) : "l"(p));
    return a;
}

__global__ void __launch_bounds__(256) coo_spmv_tma_kernel(
    const float* __restrict__ x,
    const float* __restrict__ vals,
    const int*   __restrict__ rows,
    const int*   __restrict__ cols,
    float*       __restrict__ out,
    int nnz)
{
    __shared__ __align__(128) float sv[TILE_NNZ];
    __shared__ __align__(128) int   sr[TILE_NNZ];
    __shared__ __align__(128) int   sc[TILE_NNZ];
    __shared__ __align__(8)   uint64_t mbar;

    const long base = (long)blockIdx.x * TILE_NNZ;

    if (base + TILE_NNZ <= nnz) {
        // ---- Full tile: TMA bulk-copy the three 4KB stream slices ----
        const uint32_t mb = smem_u32(&mbar);
        if (threadIdx.x == 0) {
            asm volatile("mbarrier.init.shared.b64 [%0], %1;"
                         :: "r"(mb), "r"(1) : "memory");
        }
        __syncthreads();

        if (threadIdx.x == 0) {
            asm volatile("mbarrier.arrive.expect_tx.shared.b64 _, [%0], %1;"
                         :: "r"(mb), "r"(3 * TILE_BYTES) : "memory");
            asm volatile(
                "cp.async.bulk.shared::cta.global.mbarrier::complete_tx::bytes "
                "[%0], [%1], %2, [%3];"
                :: "r"(smem_u32(sv)), "l"(vals + base), "r"(TILE_BYTES), "r"(mb)
                : "memory");
            asm volatile(
                "cp.async.bulk.shared::cta.global.mbarrier::complete_tx::bytes "
                "[%0], [%1], %2, [%3];"
                :: "r"(smem_u32(sr)), "l"(rows + base), "r"(TILE_BYTES), "r"(mb)
                : "memory");
            asm volatile(
                "cp.async.bulk.shared::cta.global.mbarrier::complete_tx::bytes "
                "[%0], [%1], %2, [%3];"
                :: "r"(smem_u32(sc)), "l"(cols + base), "r"(TILE_BYTES), "r"(mb)
                : "memory");
        }

        // Wait for the tile (parity 0; mbarrier used once per launch).
        {
            uint32_t done;
            asm volatile(
                "{ .reg .pred p;\n"
                "  mbarrier.try_wait.parity.acquire.cta.shared::cta.b64 p, [%1], %2;\n"
                "  selp.b32 %0, 1, 0, p; }"
                : "=r"(done) : "r"(mb), "r"(0) : "memory");
            if (!done) {
                asm volatile(
                    "{ .reg .pred P1;\n"
                    "WAIT_LOOP_%=:\n"
                    "  mbarrier.try_wait.parity.acquire.cta.shared::cta.b64 P1, [%0], %1, 0x989680;\n"
                    "  @P1 bra.uni WAIT_DONE_%=;\n"
                    "  bra.uni WAIT_LOOP_%=;\n"
                    "WAIT_DONE_%=: }"
                    :: "r"(mb), "r"(0) : "memory");
            }
        }

        // ---- Consume from smem crossbar (conflict-free LDS.128) ----
        const int t = threadIdx.x;
        float4 v = reinterpret_cast<const float4*>(sv)[t];
        int4   r = reinterpret_cast<const int4*>(sr)[t];
        int4   c = reinterpret_cast<const int4*>(sc)[t];

        float x0 = __ldg(&x[c.x]);
        float x1 = __ldg(&x[c.y]);
        float x2 = __ldg(&x[c.z]);
        float x3 = __ldg(&x[c.w]);

        atomicAdd(&out[r.x], v.x * x0);
        atomicAdd(&out[r.y], v.y * x1);
        atomicAdd(&out[r.z], v.z * x2);
        atomicAdd(&out[r.w], v.w * x3);
    } else {
        // ---- Partial tail tile (unused for this shape, kept correct) ----
        for (long i = base + threadIdx.x; i < nnz; i += blockDim.x) {
            atomicAdd(&out[rows[i]], vals[i] * __ldg(&x[cols[i]]));
        }
    }
}

extern "C" void kernel_launch(void* const* d_in, const int* in_sizes, int n_in,
                              void* d_out, int out_size) {
    const float* x    = (const float*)d_in[0];
    const float* vals = (const float*)d_in[1];
    const int*   rows = (const int*)d_in[2];
    const int*   cols = (const int*)d_in[3];
    float* out = (float*)d_out;

    const int nnz = in_sizes[1];

    // Zero-init output (harness poisons it).
    cudaMemsetAsync(out, 0, (size_t)out_size * sizeof(float), 0);

    int blocks = (nnz + TILE_NNZ - 1) / TILE_NNZ;   // 8192 for this shape
    coo_spmv_tma_kernel<<<blocks, 256>>>(x, vals, rows, cols, out, nnz);
}